// round 13
// baseline (speedup 1.0000x reference)
#include <cuda_runtime.h>
#include <cuda_bf16.h>
#include <cstdint>

// Problem constants
#define N_NEURONS 80
#define TBL 256
#define LATENT 128
#define N_GRAPHS 64
#define N_NODES (N_GRAPHS * N_NEURONS)   // 5120
#define N_EDGES (N_NODES * 32)           // 163840
#define N2 (N_NEURONS * N_NEURONS)       // 6400
#define H1 (2 * N2)                      // 12800
#define SK1 4
#define SK2 8

// Scratch (device globals; no allocation allowed)
__device__ float g_h[N_NODES * LATENT];
__device__ int   g_degi[N_NODES];
__device__ int   g_off[N_NODES];
__device__ int   g_cur[N_NODES];
__device__ int   g_csr[N_EDGES];
__device__ float g_dinv[N_NODES];
__device__ float g_agg[N_NODES * LATENT];
__device__ float g_zz[N_GRAPHS * N2];
__device__ float g_z1[N_GRAPHS * H1];
__device__ float g_p1[SK1 * N_GRAPHS * H1];
__device__ float g_p2[SK2 * N_GRAPHS * N2];

// ---------------------------------------------------------------------------
// cp.async helpers
// ---------------------------------------------------------------------------
__device__ __forceinline__ void cp_async16(void* smem, const void* gmem) {
    unsigned saddr = (unsigned)__cvta_generic_to_shared(smem);
    asm volatile("cp.async.cg.shared.global [%0], [%1], 16;" :: "r"(saddr), "l"(gmem));
}
__device__ __forceinline__ void cp_commit() {
    asm volatile("cp.async.commit_group;");
}
template <int N>
__device__ __forceinline__ void cp_wait() {
    asm volatile("cp.async.wait_group %0;" :: "n"(N));
}

// ---------------------------------------------------------------------------
// mma / ldmatrix helpers
// ---------------------------------------------------------------------------
__device__ __forceinline__ void ldm_x4(uint32_t* r, const void* p) {
    uint32_t a = (uint32_t)__cvta_generic_to_shared(p);
    asm volatile("ldmatrix.sync.aligned.m8n8.x4.shared.b16 {%0,%1,%2,%3}, [%4];"
        : "=r"(r[0]), "=r"(r[1]), "=r"(r[2]), "=r"(r[3]) : "r"(a));
}
__device__ __forceinline__ void ldm_x4_t(uint32_t* r, const void* p) {
    uint32_t a = (uint32_t)__cvta_generic_to_shared(p);
    asm volatile("ldmatrix.sync.aligned.m8n8.x4.trans.shared.b16 {%0,%1,%2,%3}, [%4];"
        : "=r"(r[0]), "=r"(r[1]), "=r"(r[2]), "=r"(r[3]) : "r"(a));
}
__device__ __forceinline__ void mma_bf16(float* c, const uint32_t* a, const uint32_t* b) {
    asm volatile(
        "mma.sync.aligned.m16n8k16.row.col.f32.bf16.bf16.f32 "
        "{%0,%1,%2,%3}, {%4,%5,%6,%7}, {%8,%9}, {%0,%1,%2,%3};"
        : "+f"(c[0]), "+f"(c[1]), "+f"(c[2]), "+f"(c[3])
        : "r"(a[0]), "r"(a[1]), "r"(a[2]), "r"(a[3]), "r"(b[0]), "r"(b[1]));
}

// ---------------------------------------------------------------------------
// Zero degree counters
// ---------------------------------------------------------------------------
__global__ void zero_deg_kernel() {
    int i = blockIdx.x * blockDim.x + threadIdx.x;
    if (i < N_NODES) g_degi[i] = 0;
}

// ---------------------------------------------------------------------------
// h = x @ Wg   [5120,256] @ [256,128]
// ---------------------------------------------------------------------------
__global__ __launch_bounds__(128) void gemm_h_kernel(
    const float* __restrict__ x, const float* __restrict__ Wg) {
    __shared__ float xs[4][TBL];
    int node0 = blockIdx.x * 4;
    int j = threadIdx.x;

    for (int idx = threadIdx.x; idx < 4 * TBL; idx += 128) {
        xs[idx / TBL][idx % TBL] = x[node0 * TBL + idx];
    }
    __syncthreads();

    float acc0 = 0.f, acc1 = 0.f, acc2 = 0.f, acc3 = 0.f;
#pragma unroll 4
    for (int k = 0; k < TBL; k++) {
        float w = Wg[k * LATENT + j];
        acc0 += xs[0][k] * w;
        acc1 += xs[1][k] * w;
        acc2 += xs[2][k] * w;
        acc3 += xs[3][k] * w;
    }
    g_h[(node0 + 0) * LATENT + j] = acc0;
    g_h[(node0 + 1) * LATENT + j] = acc1;
    g_h[(node0 + 2) * LATENT + j] = acc2;
    g_h[(node0 + 3) * LATENT + j] = acc3;
}

// ---------------------------------------------------------------------------
// Degree (int)
// ---------------------------------------------------------------------------
__global__ void deg_kernel(const int* __restrict__ ei) {
    int e = blockIdx.x * blockDim.x + threadIdx.x;
    if (e < N_EDGES) atomicAdd(&g_degi[ei[N_EDGES + e]], 1);
}

// ---------------------------------------------------------------------------
// Single-block exclusive scan over 5120 degrees -> offsets, cursors, dinv
// ---------------------------------------------------------------------------
__global__ __launch_bounds__(1024) void scan_kernel() {
    __shared__ int ps[1024];
    int t = threadIdx.x;
    int base = t * 5;

    int loc[5];
    int run = 0;
#pragma unroll
    for (int j = 0; j < 5; j++) { loc[j] = run; run += g_degi[base + j]; }
    ps[t] = run;
    __syncthreads();

    // Hillis-Steele inclusive scan
    for (int off = 1; off < 1024; off <<= 1) {
        int v = (t >= off) ? ps[t - off] : 0;
        __syncthreads();
        ps[t] += v;
        __syncthreads();
    }
    int pre = (t > 0) ? ps[t - 1] : 0;

#pragma unroll
    for (int j = 0; j < 5; j++) {
        int i = base + j;
        int o = pre + loc[j];
        g_off[i] = o;
        g_cur[i] = o;
        int d = g_degi[i];
        g_dinv[i] = (d > 0) ? rsqrtf((float)d) : 0.0f;
    }
}

// ---------------------------------------------------------------------------
// Fill CSR: src ids bucketed by dst
// ---------------------------------------------------------------------------
__global__ void fill_kernel(const int* __restrict__ ei) {
    int e = blockIdx.x * blockDim.x + threadIdx.x;
    if (e >= N_EDGES) return;
    int s = ei[e];
    int d = ei[N_EDGES + e];
    int pos = atomicAdd(&g_cur[d], 1);
    g_csr[pos] = s;
}

// ---------------------------------------------------------------------------
// Gather: agg[n] = dinv[n] * sum_{s in csr(n)} dinv[s] * h[s]
// One warp per node; lane covers 4 columns (float4). No atomics.
// ---------------------------------------------------------------------------
__global__ __launch_bounds__(256) void gather_kernel() {
    int wid = threadIdx.x >> 5, lane = threadIdx.x & 31;
    int node = blockIdx.x * 8 + wid;
    if (node >= N_NODES) return;

    int start = g_off[node];
    int cnt = g_degi[node];
    const float4* __restrict__ h4 = reinterpret_cast<const float4*>(g_h);

    float4 acc = make_float4(0.f, 0.f, 0.f, 0.f);
    int j = 0;
    for (; j + 4 <= cnt; j += 4) {
        int s0 = g_csr[start + j + 0];
        int s1 = g_csr[start + j + 1];
        int s2 = g_csr[start + j + 2];
        int s3 = g_csr[start + j + 3];
        float w0 = g_dinv[s0], w1 = g_dinv[s1], w2 = g_dinv[s2], w3 = g_dinv[s3];
        float4 v0 = h4[(size_t)s0 * 32 + lane];
        float4 v1 = h4[(size_t)s1 * 32 + lane];
        float4 v2 = h4[(size_t)s2 * 32 + lane];
        float4 v3 = h4[(size_t)s3 * 32 + lane];
        acc.x += v0.x * w0 + v1.x * w1 + v2.x * w2 + v3.x * w3;
        acc.y += v0.y * w0 + v1.y * w1 + v2.y * w2 + v3.y * w3;
        acc.z += v0.z * w0 + v1.z * w1 + v2.z * w2 + v3.z * w3;
        acc.w += v0.w * w0 + v1.w * w1 + v2.w * w2 + v3.w * w3;
    }
    for (; j < cnt; j++) {
        int s = g_csr[start + j];
        float w = g_dinv[s];
        float4 v = h4[(size_t)s * 32 + lane];
        acc.x += v.x * w; acc.y += v.y * w; acc.z += v.z * w; acc.w += v.w * w;
    }
    float dd = g_dinv[node];
    acc.x *= dd; acc.y *= dd; acc.z *= dd; acc.w *= dd;
    reinterpret_cast<float4*>(g_agg)[(size_t)node * 32 + lane] = acc;
}

// ---------------------------------------------------------------------------
// Per-graph: z = relu(agg + bg); zz[n][m] = sum_l z[n][l]*z[m][l]
// Transposed smem + float4 micro-tile: 1 scalar + 1 LDS.128 per 4 FMA.
// ---------------------------------------------------------------------------
#define ZT_STRIDE 84
__global__ __launch_bounds__(256) void outer_kernel(const float* __restrict__ bg) {
    __shared__ alignas(16) float zsT[LATENT][ZT_STRIDE];
    int g = blockIdx.x;

    for (int idx = threadIdx.x; idx < N_NEURONS * LATENT; idx += 256) {
        int n = idx >> 7;
        int l = idx & 127;
        float v = g_agg[((size_t)g * N_NEURONS + n) * LATENT + l] + bg[l];
        zsT[l][n] = v > 0.0f ? v : 0.0f;
    }
    __syncthreads();

    // 6400 outputs = 1600 float4 groups; thread -> (n, m0=4*mg)
    for (int p = threadIdx.x; p < N2 / 4; p += 256) {
        int n = p / (N_NEURONS / 4);
        int m0 = (p % (N_NEURONS / 4)) * 4;
        float4 acc = make_float4(0.f, 0.f, 0.f, 0.f);
#pragma unroll 4
        for (int l = 0; l < LATENT; l++) {
            float a = zsT[l][n];
            float4 v = *reinterpret_cast<const float4*>(&zsT[l][m0]);
            acc.x += a * v.x; acc.y += a * v.y; acc.z += a * v.z; acc.w += a * v.w;
        }
        *reinterpret_cast<float4*>(&g_zz[(size_t)g * N2 + n * N_NEURONS + m0]) = acc;
    }
}

// ---------------------------------------------------------------------------
// Tensor-core split-K GEMM, bf16 hi/lo 3-term split (~fp32 accuracy).
// 3-stage cp.async pipeline, 2 syncthreads per K-iter, dynamic smem (57KB).
// ---------------------------------------------------------------------------
#define BM 64
#define BN 128
#define KTO 16
#define KTR 48
#define AS_STRIDE 56
#define WS_STRIDE 136
#define A_SM_BYTES   (BM * AS_STRIDE * 2)            // 7168
#define W_SM_BYTES   (KTR * WS_STRIDE * 2)           // 13056
#define AST_BYTES    (3 * BM * KTO * 4)              // 12288
#define WST_BYTES    (3 * KTO * BN * 4)              // 24576
#define GEMM_SMEM    (A_SM_BYTES + W_SM_BYTES + AST_BYTES + WST_BYTES)  // 57088

__global__ __launch_bounds__(256) void gemm_mma_splitk(
    const float* __restrict__ A, const float* __restrict__ W,
    float* __restrict__ partial, int K, int N, int Kchunk) {
    extern __shared__ char smem_raw[];
    __nv_bfloat16 (*A_sm)[AS_STRIDE] =
        reinterpret_cast<__nv_bfloat16(*)[AS_STRIDE]>(smem_raw);
    __nv_bfloat16 (*W_sm)[WS_STRIDE] =
        reinterpret_cast<__nv_bfloat16(*)[WS_STRIDE]>(smem_raw + A_SM_BYTES);
    float (*As_stage)[BM][KTO] =
        reinterpret_cast<float(*)[BM][KTO]>(smem_raw + A_SM_BYTES + W_SM_BYTES);
    float (*Ws_stage)[KTO][BN] =
        reinterpret_cast<float(*)[KTO][BN]>(smem_raw + A_SM_BYTES + W_SM_BYTES + AST_BYTES);

    int tid = threadIdx.x;
    int wid = tid >> 5, lane = tid & 31;
    int warp_m = wid & 1;
    int warp_n = wid >> 1;
    int n0 = blockIdx.x * BN;
    int sk = blockIdx.y;
    int kbase = sk * Kchunk;
    int T = Kchunk / KTO;

    float acc[2][4][4];
#pragma unroll
    for (int mi = 0; mi < 2; mi++)
#pragma unroll
        for (int ni = 0; ni < 4; ni++)
#pragma unroll
            for (int c = 0; c < 4; c++) acc[mi][ni][c] = 0.0f;

    auto issue = [&](int s, int k0) {
        {
            int m = tid >> 2, c = tid & 3;
            cp_async16(&As_stage[s][m][c * 4], &A[(size_t)m * K + k0 + c * 4]);
        }
#pragma unroll
        for (int i = 0; i < 2; i++) {
            int c = tid + i * 256;
            int kk = c >> 5, n4 = (c & 31) * 4;
            cp_async16(&Ws_stage[s][kk][n4], &W[(size_t)(k0 + kk) * N + n0 + n4]);
        }
        cp_commit();
    };

    issue(0, kbase);
    issue(1, kbase + KTO);

    int g8 = lane >> 3, r8 = lane & 7;
    int row_off = (g8 & 1) * 8 + r8;
    int col_off = (g8 >> 1) * 8;

    for (int t = 0; t < T; t++) {
        if (t + 2 < T) {
            issue((t + 2) % 3, kbase + (t + 2) * KTO);
            cp_wait<2>();
        } else if (t + 1 < T) {
            cp_wait<1>();
        } else {
            cp_wait<0>();
        }
        __syncthreads();  // stage t visible to all; prev mma done -> bf16 free

        int s = t % 3;
        // Convert A: 512 float2 pairs -> 2 per thread
#pragma unroll
        for (int i = 0; i < 2; i++) {
            int idx = tid + i * 256;
            int m = idx >> 3, kp = idx & 7;
            float2 f = *reinterpret_cast<const float2*>(&As_stage[s][m][kp * 2]);
            __nv_bfloat162 hi = __floats2bfloat162_rn(f.x, f.y);
            __nv_bfloat162 lo = __floats2bfloat162_rn(
                f.x - __bfloat162float(hi.x), f.y - __bfloat162float(hi.y));
            *(__nv_bfloat162*)&A_sm[m][kp * 2]      = hi;
            *(__nv_bfloat162*)&A_sm[m][16 + kp * 2] = lo;
            *(__nv_bfloat162*)&A_sm[m][32 + kp * 2] = hi;
        }
        // Convert W: 1024 float2 pairs -> 4 per thread
#pragma unroll
        for (int i = 0; i < 4; i++) {
            int idx = tid + i * 256;
            int kk = idx >> 6, np = idx & 63;
            float2 f = *reinterpret_cast<const float2*>(&Ws_stage[s][kk][np * 2]);
            __nv_bfloat162 hi = __floats2bfloat162_rn(f.x, f.y);
            __nv_bfloat162 lo = __floats2bfloat162_rn(
                f.x - __bfloat162float(hi.x), f.y - __bfloat162float(hi.y));
            *(__nv_bfloat162*)&W_sm[kk][np * 2]      = hi;
            *(__nv_bfloat162*)&W_sm[16 + kk][np * 2] = hi;
            *(__nv_bfloat162*)&W_sm[32 + kk][np * 2] = lo;
        }
        __syncthreads();  // bf16 tiles ready

#pragma unroll
        for (int p = 0; p < 3; p++) {
            uint32_t afr[2][4], bfr[2][4];
#pragma unroll
            for (int mi = 0; mi < 2; mi++)
                ldm_x4(afr[mi], &A_sm[warp_m * 32 + mi * 16 + row_off][p * 16 + col_off]);
#pragma unroll
            for (int ni = 0; ni < 2; ni++)
                ldm_x4_t(bfr[ni], &W_sm[p * 16 + row_off][warp_n * 32 + ni * 16 + col_off]);
#pragma unroll
            for (int mi = 0; mi < 2; mi++) {
                mma_bf16(acc[mi][0], afr[mi], &bfr[0][0]);
                mma_bf16(acc[mi][1], afr[mi], &bfr[0][2]);
                mma_bf16(acc[mi][2], afr[mi], &bfr[1][0]);
                mma_bf16(acc[mi][3], afr[mi], &bfr[1][2]);
            }
        }
        // no trailing sync: next iteration's first sync guards bf16 reuse
    }

    int gq = lane >> 2, c2 = (lane & 3) * 2;
#pragma unroll
    for (int mi = 0; mi < 2; mi++)
#pragma unroll
        for (int ni = 0; ni < 4; ni++) {
            int col = n0 + warp_n * 32 + ni * 8 + c2;
            int row0 = warp_m * 32 + mi * 16 + gq;
            float* base = &partial[((size_t)sk * BM + row0) * N + col];
            *reinterpret_cast<float2*>(base) =
                make_float2(acc[mi][ni][0], acc[mi][ni][1]);
            *reinterpret_cast<float2*>(base + 8 * (size_t)N) =
                make_float2(acc[mi][ni][2], acc[mi][ni][3]);
        }
}

// ---------------------------------------------------------------------------
// Epilogs: sum split-K partials + bias + activation
// ---------------------------------------------------------------------------
__global__ __launch_bounds__(256) void epilog1_kernel(const float* __restrict__ b1) {
    int i = blockIdx.x * blockDim.x + threadIdx.x;
    int total4 = N_GRAPHS * H1 / 4;
    if (i >= total4) return;
    const float4* p = reinterpret_cast<const float4*>(g_p1);
    float4 s = p[i];
#pragma unroll
    for (int sk = 1; sk < SK1; sk++) {
        float4 v = p[(size_t)sk * total4 + i];
        s.x += v.x; s.y += v.y; s.z += v.z; s.w += v.w;
    }
    int col = (i * 4) % H1;
    float4 b = *reinterpret_cast<const float4*>(&b1[col]);
    s.x = fmaxf(s.x + b.x, 0.0f);
    s.y = fmaxf(s.y + b.y, 0.0f);
    s.z = fmaxf(s.z + b.z, 0.0f);
    s.w = fmaxf(s.w + b.w, 0.0f);
    reinterpret_cast<float4*>(g_z1)[i] = s;
}

__global__ __launch_bounds__(256) void epilog2_kernel(const float* __restrict__ b2,
                                                      float* __restrict__ out) {
    int i = blockIdx.x * blockDim.x + threadIdx.x;
    int total4 = N_GRAPHS * N2 / 4;
    if (i >= total4) return;
    const float4* p = reinterpret_cast<const float4*>(g_p2);
    float4 s = p[i];
#pragma unroll
    for (int sk = 1; sk < SK2; sk++) {
        float4 v = p[(size_t)sk * total4 + i];
        s.x += v.x; s.y += v.y; s.z += v.z; s.w += v.w;
    }
    int col = (i * 4) % N2;
    float4 b = *reinterpret_cast<const float4*>(&b2[col]);
    s.x = 1.0f / (1.0f + __expf(-(s.x + b.x)));
    s.y = 1.0f / (1.0f + __expf(-(s.y + b.y)));
    s.z = 1.0f / (1.0f + __expf(-(s.z + b.z)));
    s.w = 1.0f / (1.0f + __expf(-(s.w + b.w)));
    reinterpret_cast<float4*>(out)[i] = s;
}

// ---------------------------------------------------------------------------
extern "C" void kernel_launch(void* const* d_in, const int* in_sizes, int n_in,
                              void* d_out, int out_size) {
    const float* x  = (const float*)d_in[0];
    const int* ei   = (const int*)d_in[1];
    const float* Wg = (const float*)d_in[2];
    const float* bg = (const float*)d_in[3];
    const float* W1 = (const float*)d_in[4];
    const float* b1 = (const float*)d_in[5];
    const float* W2 = (const float*)d_in[6];
    const float* b2 = (const float*)d_in[7];
    float* out = (float*)d_out;

    float *zz, *z1, *p1, *p2;
    cudaGetSymbolAddress((void**)&zz, g_zz);
    cudaGetSymbolAddress((void**)&z1, g_z1);
    cudaGetSymbolAddress((void**)&p1, g_p1);
    cudaGetSymbolAddress((void**)&p2, g_p2);

    static bool attr_set = false;
    if (!attr_set) {
        cudaFuncSetAttribute(gemm_mma_splitk,
                             cudaFuncAttributeMaxDynamicSharedMemorySize, GEMM_SMEM);
        attr_set = true;
    }

    // 1. zero degree counters
    zero_deg_kernel<<<(N_NODES + 255) / 256, 256>>>();
    // 2. h = x @ Wg
    gemm_h_kernel<<<N_NODES / 4, 128>>>(x, Wg);
    // 3. degree
    deg_kernel<<<(N_EDGES + 255) / 256, 256>>>(ei);
    // 4. exclusive scan -> offsets/cursors/dinv
    scan_kernel<<<1, 1024>>>();
    // 5. fill CSR
    fill_kernel<<<(N_EDGES + 255) / 256, 256>>>(ei);
    // 6. gather (no atomics)
    gather_kernel<<<N_NODES / 8, 256>>>();
    // 7. relu + per-graph outer product
    outer_kernel<<<N_GRAPHS, 256>>>(bg);
    // 8. GEMM1 partials: [64,6400]@[6400,12800], split-K=4 -> 400 blocks
    {
        dim3 grid(H1 / BN, SK1);
        gemm_mma_splitk<<<grid, 256, GEMM_SMEM>>>(zz, W1, p1, N2, H1, N2 / SK1);
    }
    // 9. z1 = relu(sum + b1)
    {
        int total4 = N_GRAPHS * H1 / 4;
        epilog1_kernel<<<(total4 + 255) / 256, 256>>>(b1);
    }
    // 10. GEMM2 partials: [64,12800]@[12800,6400], split-K=8 -> 400 blocks
    {
        dim3 grid(N2 / BN, SK2);
        gemm_mma_splitk<<<grid, 256, GEMM_SMEM>>>(z1, W2, p2, H1, N2, H1 / SK2);
    }
    // 11. out = sigmoid(sum + b2)
    {
        int total4 = N_GRAPHS * N2 / 4;
        epilog2_kernel<<<(total4 + 255) / 256, 256>>>(b2, out);
    }
}

// round 14
// speedup vs baseline: 1.5045x; 1.5045x over previous
#include <cuda_runtime.h>
#include <cuda_bf16.h>
#include <cstdint>

// Problem constants
#define N_NEURONS 80
#define TBL 256
#define LATENT 128
#define N_GRAPHS 64
#define N_NODES (N_GRAPHS * N_NEURONS)   // 5120
#define N_EDGES (N_NODES * 32)           // 163840
#define N2 (N_NEURONS * N_NEURONS)       // 6400
#define H1 (2 * N2)                      // 12800
#define SK1 4                            // split-K for GEMM1
#define SK2 8                            // split-K for GEMM2

// Scratch (device globals; no allocation allowed)
__device__ float g_h[N_NODES * LATENT];
__device__ float g_deg[N_NODES];
__device__ float g_dinv[N_NODES];
__device__ float g_agg[N_NODES * LATENT];
__device__ float g_zz[N_GRAPHS * N2];
__device__ float g_z1[N_GRAPHS * H1];
__device__ float g_p1[SK1 * N_GRAPHS * H1];
__device__ float g_p2[SK2 * N_GRAPHS * N2];

// ---------------------------------------------------------------------------
// cp.async helpers
// ---------------------------------------------------------------------------
__device__ __forceinline__ void cp_async16(void* smem, const void* gmem) {
    unsigned saddr = (unsigned)__cvta_generic_to_shared(smem);
    asm volatile("cp.async.cg.shared.global [%0], [%1], 16;" :: "r"(saddr), "l"(gmem));
}
__device__ __forceinline__ void cp_commit() {
    asm volatile("cp.async.commit_group;");
}
template <int N>
__device__ __forceinline__ void cp_wait() {
    asm volatile("cp.async.wait_group %0;" :: "n"(N));
}

// ---------------------------------------------------------------------------
// mma / ldmatrix helpers
// ---------------------------------------------------------------------------
__device__ __forceinline__ void ldm_x4(uint32_t* r, const void* p) {
    uint32_t a = (uint32_t)__cvta_generic_to_shared(p);
    asm volatile("ldmatrix.sync.aligned.m8n8.x4.shared.b16 {%0,%1,%2,%3}, [%4];"
        : "=r"(r[0]), "=r"(r[1]), "=r"(r[2]), "=r"(r[3]) : "r"(a));
}
__device__ __forceinline__ void ldm_x4_t(uint32_t* r, const void* p) {
    uint32_t a = (uint32_t)__cvta_generic_to_shared(p);
    asm volatile("ldmatrix.sync.aligned.m8n8.x4.trans.shared.b16 {%0,%1,%2,%3}, [%4];"
        : "=r"(r[0]), "=r"(r[1]), "=r"(r[2]), "=r"(r[3]) : "r"(a));
}
__device__ __forceinline__ void mma_bf16(float* c, const uint32_t* a, const uint32_t* b) {
    asm volatile(
        "mma.sync.aligned.m16n8k16.row.col.f32.bf16.bf16.f32 "
        "{%0,%1,%2,%3}, {%4,%5,%6,%7}, {%8,%9}, {%0,%1,%2,%3};"
        : "+f"(c[0]), "+f"(c[1]), "+f"(c[2]), "+f"(c[3])
        : "r"(a[0]), "r"(a[1]), "r"(a[2]), "r"(a[3]), "r"(b[0]), "r"(b[1]));
}

// ---------------------------------------------------------------------------
// Zero deg + agg
// ---------------------------------------------------------------------------
__global__ void zero_kernel() {
    int i = blockIdx.x * blockDim.x + threadIdx.x;
    int total = N_NODES * LATENT;
    if (i < total) g_agg[i] = 0.0f;
    if (i < N_NODES) g_deg[i] = 0.0f;
}

// ---------------------------------------------------------------------------
// h = x @ Wg   [5120,256] @ [256,128]
// ---------------------------------------------------------------------------
__global__ __launch_bounds__(128) void gemm_h_kernel(
    const float* __restrict__ x, const float* __restrict__ Wg) {
    __shared__ float xs[4][TBL];
    int node0 = blockIdx.x * 4;
    int j = threadIdx.x;

    for (int idx = threadIdx.x; idx < 4 * TBL; idx += 128) {
        xs[idx / TBL][idx % TBL] = x[node0 * TBL + idx];
    }
    __syncthreads();

    float acc0 = 0.f, acc1 = 0.f, acc2 = 0.f, acc3 = 0.f;
#pragma unroll 4
    for (int k = 0; k < TBL; k++) {
        float w = Wg[k * LATENT + j];
        acc0 += xs[0][k] * w;
        acc1 += xs[1][k] * w;
        acc2 += xs[2][k] * w;
        acc3 += xs[3][k] * w;
    }
    g_h[(node0 + 0) * LATENT + j] = acc0;
    g_h[(node0 + 1) * LATENT + j] = acc1;
    g_h[(node0 + 2) * LATENT + j] = acc2;
    g_h[(node0 + 3) * LATENT + j] = acc3;
}

// ---------------------------------------------------------------------------
// Degree + dinv
// ---------------------------------------------------------------------------
__global__ void deg_kernel(const int* __restrict__ ei) {
    int e = blockIdx.x * blockDim.x + threadIdx.x;
    if (e < N_EDGES) atomicAdd(&g_deg[ei[N_EDGES + e]], 1.0f);
}

__global__ void dinv_kernel() {
    int i = blockIdx.x * blockDim.x + threadIdx.x;
    if (i < N_NODES) {
        float d = g_deg[i];
        g_dinv[i] = (d > 0.0f) ? rsqrtf(fmaxf(d, 1.0f)) : 0.0f;
    }
}

// ---------------------------------------------------------------------------
// agg[dst] += h[src] * (dinv[src]*dinv[dst]); one warp per edge.
// One red.global.add.v4.f32 per lane (16B, no return) instead of 4 scalar
// atomics: 21M -> 5.2M LTS-atomic-ALU ops.
// ---------------------------------------------------------------------------
__global__ __launch_bounds__(256) void scatter_kernel(const int* __restrict__ ei) {
    long long tid = (long long)blockIdx.x * blockDim.x + threadIdx.x;
    int e = (int)(tid >> 5);
    int lane = (int)(tid & 31);
    if (e >= N_EDGES) return;
    int s = ei[e];
    int d = ei[N_EDGES + e];
    float norm = g_dinv[s] * g_dinv[d];
    float4 v = reinterpret_cast<const float4*>(&g_h[(size_t)s * LATENT])[lane];
    float* ag = &g_agg[(size_t)d * LATENT + lane * 4];
    asm volatile("red.global.add.v4.f32 [%0], {%1, %2, %3, %4};"
                 :: "l"(ag), "f"(v.x * norm), "f"(v.y * norm),
                    "f"(v.z * norm), "f"(v.w * norm)
                 : "memory");
}

// ---------------------------------------------------------------------------
// Per-graph: z = relu(agg + bg); zz[n][m] = sum_l z[n][l]*z[m][l]
// Transposed smem + float4 micro-tile: 1 scalar + 1 LDS.128 per 4 FMA.
// ---------------------------------------------------------------------------
#define ZT_STRIDE 84
__global__ __launch_bounds__(256) void outer_kernel(const float* __restrict__ bg) {
    __shared__ alignas(16) float zsT[LATENT][ZT_STRIDE];
    int g = blockIdx.x;

    for (int idx = threadIdx.x; idx < N_NEURONS * LATENT; idx += 256) {
        int n = idx >> 7;
        int l = idx & 127;
        float v = g_agg[((size_t)g * N_NEURONS + n) * LATENT + l] + bg[l];
        zsT[l][n] = v > 0.0f ? v : 0.0f;
    }
    __syncthreads();

    for (int p = threadIdx.x; p < N2 / 4; p += 256) {
        int n = p / (N_NEURONS / 4);
        int m0 = (p % (N_NEURONS / 4)) * 4;
        float4 acc = make_float4(0.f, 0.f, 0.f, 0.f);
#pragma unroll 4
        for (int l = 0; l < LATENT; l++) {
            float a = zsT[l][n];
            float4 v = *reinterpret_cast<const float4*>(&zsT[l][m0]);
            acc.x += a * v.x; acc.y += a * v.y; acc.z += a * v.z; acc.w += a * v.w;
        }
        *reinterpret_cast<float4*>(&g_zz[(size_t)g * N2 + n * N_NEURONS + m0]) = acc;
    }
}

// ---------------------------------------------------------------------------
// Tensor-core split-K GEMM with bf16 hi/lo 3-term split (~fp32 accuracy).
//   2-stage cp.async pipeline (proven), static smem, 2 syncthreads per K-iter.
// ---------------------------------------------------------------------------
#define BM 64
#define BN 128
#define KTO 16
#define KTR 48
#define AS_STRIDE 56
#define WS_STRIDE 136

__global__ __launch_bounds__(256) void gemm_mma_splitk(
    const float* __restrict__ A, const float* __restrict__ W,
    float* __restrict__ partial, int K, int N, int Kchunk) {
    __shared__ __nv_bfloat16 A_sm[BM][AS_STRIDE];
    __shared__ __nv_bfloat16 W_sm[KTR][WS_STRIDE];
    __shared__ alignas(16) float As_stage[2][BM][KTO];
    __shared__ alignas(16) float Ws_stage[2][KTO][BN];

    int tid = threadIdx.x;
    int wid = tid >> 5, lane = tid & 31;
    int warp_m = wid & 1;
    int warp_n = wid >> 1;
    int n0 = blockIdx.x * BN;
    int sk = blockIdx.y;
    int kbase = sk * Kchunk;
    int T = Kchunk / KTO;

    float acc[2][4][4];
#pragma unroll
    for (int mi = 0; mi < 2; mi++)
#pragma unroll
        for (int ni = 0; ni < 4; ni++)
#pragma unroll
            for (int c = 0; c < 4; c++) acc[mi][ni][c] = 0.0f;

    auto issue = [&](int s, int k0) {
        {
            int m = tid >> 2, c = tid & 3;
            cp_async16(&As_stage[s][m][c * 4], &A[(size_t)m * K + k0 + c * 4]);
        }
#pragma unroll
        for (int i = 0; i < 2; i++) {
            int c = tid + i * 256;
            int kk = c >> 5, n4 = (c & 31) * 4;
            cp_async16(&Ws_stage[s][kk][n4], &W[(size_t)(k0 + kk) * N + n0 + n4]);
        }
        cp_commit();
    };

    issue(0, kbase);

    int g8 = lane >> 3, r8 = lane & 7;
    int row_off = (g8 & 1) * 8 + r8;
    int col_off = (g8 >> 1) * 8;

    for (int t = 0; t < T; t++) {
        if (t + 1 < T) {
            issue((t + 1) & 1, kbase + (t + 1) * KTO);
            cp_wait<1>();
        } else {
            cp_wait<0>();
        }
        __syncthreads();  // stage t visible; all threads past prev iter's mma

        int s = t & 1;
        // Convert A: 512 float2 pairs -> 2 per thread
#pragma unroll
        for (int i = 0; i < 2; i++) {
            int idx = tid + i * 256;
            int m = idx >> 3, kp = idx & 7;
            float2 f = *reinterpret_cast<const float2*>(&As_stage[s][m][kp * 2]);
            __nv_bfloat162 hi = __floats2bfloat162_rn(f.x, f.y);
            __nv_bfloat162 lo = __floats2bfloat162_rn(
                f.x - __bfloat162float(hi.x), f.y - __bfloat162float(hi.y));
            *(__nv_bfloat162*)&A_sm[m][kp * 2]      = hi;
            *(__nv_bfloat162*)&A_sm[m][16 + kp * 2] = lo;
            *(__nv_bfloat162*)&A_sm[m][32 + kp * 2] = hi;
        }
        // Convert W: 1024 float2 pairs -> 4 per thread
#pragma unroll
        for (int i = 0; i < 4; i++) {
            int idx = tid + i * 256;
            int kk = idx >> 6, np = idx & 63;
            float2 f = *reinterpret_cast<const float2*>(&Ws_stage[s][kk][np * 2]);
            __nv_bfloat162 hi = __floats2bfloat162_rn(f.x, f.y);
            __nv_bfloat162 lo = __floats2bfloat162_rn(
                f.x - __bfloat162float(hi.x), f.y - __bfloat162float(hi.y));
            *(__nv_bfloat162*)&W_sm[kk][np * 2]      = hi;
            *(__nv_bfloat162*)&W_sm[16 + kk][np * 2] = hi;
            *(__nv_bfloat162*)&W_sm[32 + kk][np * 2] = lo;
        }
        __syncthreads();  // bf16 tiles ready

#pragma unroll
        for (int p = 0; p < 3; p++) {
            uint32_t afr[2][4], bfr[2][4];
#pragma unroll
            for (int mi = 0; mi < 2; mi++)
                ldm_x4(afr[mi], &A_sm[warp_m * 32 + mi * 16 + row_off][p * 16 + col_off]);
#pragma unroll
            for (int ni = 0; ni < 2; ni++)
                ldm_x4_t(bfr[ni], &W_sm[p * 16 + row_off][warp_n * 32 + ni * 16 + col_off]);
#pragma unroll
            for (int mi = 0; mi < 2; mi++) {
                mma_bf16(acc[mi][0], afr[mi], &bfr[0][0]);
                mma_bf16(acc[mi][1], afr[mi], &bfr[0][2]);
                mma_bf16(acc[mi][2], afr[mi], &bfr[1][0]);
                mma_bf16(acc[mi][3], afr[mi], &bfr[1][2]);
            }
        }
        // no trailing sync: next iteration's first barrier guards bf16 reuse
    }

    int gq = lane >> 2, c2 = (lane & 3) * 2;
#pragma unroll
    for (int mi = 0; mi < 2; mi++)
#pragma unroll
        for (int ni = 0; ni < 4; ni++) {
            int col = n0 + warp_n * 32 + ni * 8 + c2;
            int row0 = warp_m * 32 + mi * 16 + gq;
            float* base = &partial[((size_t)sk * BM + row0) * N + col];
            *reinterpret_cast<float2*>(base) =
                make_float2(acc[mi][ni][0], acc[mi][ni][1]);
            *reinterpret_cast<float2*>(base + 8 * (size_t)N) =
                make_float2(acc[mi][ni][2], acc[mi][ni][3]);
        }
}

// ---------------------------------------------------------------------------
// Epilogs: sum split-K partials + bias + activation
// ---------------------------------------------------------------------------
__global__ __launch_bounds__(256) void epilog1_kernel(const float* __restrict__ b1) {
    int i = blockIdx.x * blockDim.x + threadIdx.x;
    int total4 = N_GRAPHS * H1 / 4;
    if (i >= total4) return;
    const float4* p = reinterpret_cast<const float4*>(g_p1);
    float4 s = p[i];
#pragma unroll
    for (int sk = 1; sk < SK1; sk++) {
        float4 v = p[(size_t)sk * total4 + i];
        s.x += v.x; s.y += v.y; s.z += v.z; s.w += v.w;
    }
    int col = (i * 4) % H1;
    float4 b = *reinterpret_cast<const float4*>(&b1[col]);
    s.x = fmaxf(s.x + b.x, 0.0f);
    s.y = fmaxf(s.y + b.y, 0.0f);
    s.z = fmaxf(s.z + b.z, 0.0f);
    s.w = fmaxf(s.w + b.w, 0.0f);
    reinterpret_cast<float4*>(g_z1)[i] = s;
}

__global__ __launch_bounds__(256) void epilog2_kernel(const float* __restrict__ b2,
                                                      float* __restrict__ out) {
    int i = blockIdx.x * blockDim.x + threadIdx.x;
    int total4 = N_GRAPHS * N2 / 4;
    if (i >= total4) return;
    const float4* p = reinterpret_cast<const float4*>(g_p2);
    float4 s = p[i];
#pragma unroll
    for (int sk = 1; sk < SK2; sk++) {
        float4 v = p[(size_t)sk * total4 + i];
        s.x += v.x; s.y += v.y; s.z += v.z; s.w += v.w;
    }
    int col = (i * 4) % N2;
    float4 b = *reinterpret_cast<const float4*>(&b2[col]);
    s.x = 1.0f / (1.0f + __expf(-(s.x + b.x)));
    s.y = 1.0f / (1.0f + __expf(-(s.y + b.y)));
    s.z = 1.0f / (1.0f + __expf(-(s.z + b.z)));
    s.w = 1.0f / (1.0f + __expf(-(s.w + b.w)));
    reinterpret_cast<float4*>(out)[i] = s;
}

// ---------------------------------------------------------------------------
extern "C" void kernel_launch(void* const* d_in, const int* in_sizes, int n_in,
                              void* d_out, int out_size) {
    const float* x  = (const float*)d_in[0];
    const int* ei   = (const int*)d_in[1];
    const float* Wg = (const float*)d_in[2];
    const float* bg = (const float*)d_in[3];
    const float* W1 = (const float*)d_in[4];
    const float* b1 = (const float*)d_in[5];
    const float* W2 = (const float*)d_in[6];
    const float* b2 = (const float*)d_in[7];
    float* out = (float*)d_out;

    float *zz, *z1, *p1, *p2;
    cudaGetSymbolAddress((void**)&zz, g_zz);
    cudaGetSymbolAddress((void**)&z1, g_z1);
    cudaGetSymbolAddress((void**)&p1, g_p1);
    cudaGetSymbolAddress((void**)&p2, g_p2);

    // 1. zero deg + agg
    {
        int total = N_NODES * LATENT;
        zero_kernel<<<(total + 255) / 256, 256>>>();
    }
    // 2. h = x @ Wg
    gemm_h_kernel<<<N_NODES / 4, 128>>>(x, Wg);
    // 3. degree
    deg_kernel<<<(N_EDGES + 255) / 256, 256>>>(ei);
    // 4. dinv
    dinv_kernel<<<(N_NODES + 255) / 256, 256>>>();
    // 5. scatter-add messages (vector red)
    {
        long long threads = (long long)N_EDGES * 32;
        scatter_kernel<<<(unsigned)((threads + 255) / 256), 256>>>(ei);
    }
    // 6. relu + per-graph outer product
    outer_kernel<<<N_GRAPHS, 256>>>(bg);
    // 7. GEMM1 partials: [64,6400]@[6400,12800], split-K=4 -> 400 blocks
    {
        dim3 grid(H1 / BN, SK1);
        gemm_mma_splitk<<<grid, 256>>>(zz, W1, p1, N2, H1, N2 / SK1);
    }
    // 8. z1 = relu(sum + b1)
    {
        int total4 = N_GRAPHS * H1 / 4;
        epilog1_kernel<<<(total4 + 255) / 256, 256>>>(b1);
    }
    // 9. GEMM2 partials: [64,12800]@[12800,6400], split-K=8 -> 400 blocks
    {
        dim3 grid(N2 / BN, SK2);
        gemm_mma_splitk<<<grid, 256>>>(z1, W2, p2, H1, N2, H1 / SK2);
    }
    // 10. out = sigmoid(sum + b2)
    {
        int total4 = N_GRAPHS * N2 / 4;
        epilog2_kernel<<<(total4 + 255) / 256, 256>>>(b2, out);
    }
}

// round 15
// speedup vs baseline: 1.7968x; 1.1943x over previous
#include <cuda_runtime.h>
#include <cuda_bf16.h>
#include <cstdint>

// Problem constants
#define N_NEURONS 80
#define TBL 256
#define LATENT 128
#define N_GRAPHS 64
#define N_NODES (N_GRAPHS * N_NEURONS)   // 5120
#define N_EDGES (N_NODES * 32)           // 163840
#define N2 (N_NEURONS * N_NEURONS)       // 6400
#define H1 (2 * N2)                      // 12800
#define SK1 4                            // split-K for GEMM1
#define SK2 8                            // split-K for GEMM2

// Scratch (device globals; no allocation allowed)
__device__ float g_h[N_NODES * LATENT];
__device__ float g_deg[N_NODES];
__device__ float g_dinv[N_NODES];
__device__ float g_agg[N_NODES * LATENT];
__device__ __nv_bfloat16 g_zz_hi[N_GRAPHS * N2];
__device__ __nv_bfloat16 g_zz_lo[N_GRAPHS * N2];
__device__ __nv_bfloat16 g_z1_hi[N_GRAPHS * H1];
__device__ __nv_bfloat16 g_z1_lo[N_GRAPHS * H1];
__device__ float g_p1[SK1 * N_GRAPHS * H1];
__device__ float g_p2[SK2 * N_GRAPHS * N2];

// ---------------------------------------------------------------------------
// cp.async helpers
// ---------------------------------------------------------------------------
__device__ __forceinline__ void cp_async16(void* smem, const void* gmem) {
    unsigned saddr = (unsigned)__cvta_generic_to_shared(smem);
    asm volatile("cp.async.cg.shared.global [%0], [%1], 16;" :: "r"(saddr), "l"(gmem));
}
__device__ __forceinline__ void cp_commit() {
    asm volatile("cp.async.commit_group;");
}
template <int N>
__device__ __forceinline__ void cp_wait() {
    asm volatile("cp.async.wait_group %0;" :: "n"(N));
}

// ---------------------------------------------------------------------------
// mma / ldmatrix helpers
// ---------------------------------------------------------------------------
__device__ __forceinline__ void ldm_x4(uint32_t* r, const void* p) {
    uint32_t a = (uint32_t)__cvta_generic_to_shared(p);
    asm volatile("ldmatrix.sync.aligned.m8n8.x4.shared.b16 {%0,%1,%2,%3}, [%4];"
        : "=r"(r[0]), "=r"(r[1]), "=r"(r[2]), "=r"(r[3]) : "r"(a));
}
__device__ __forceinline__ void ldm_x4_t(uint32_t* r, const void* p) {
    uint32_t a = (uint32_t)__cvta_generic_to_shared(p);
    asm volatile("ldmatrix.sync.aligned.m8n8.x4.trans.shared.b16 {%0,%1,%2,%3}, [%4];"
        : "=r"(r[0]), "=r"(r[1]), "=r"(r[2]), "=r"(r[3]) : "r"(a));
}
__device__ __forceinline__ void mma_bf16(float* c, const uint32_t* a, const uint32_t* b) {
    asm volatile(
        "mma.sync.aligned.m16n8k16.row.col.f32.bf16.bf16.f32 "
        "{%0,%1,%2,%3}, {%4,%5,%6,%7}, {%8,%9}, {%0,%1,%2,%3};"
        : "+f"(c[0]), "+f"(c[1]), "+f"(c[2]), "+f"(c[3])
        : "r"(a[0]), "r"(a[1]), "r"(a[2]), "r"(a[3]), "r"(b[0]), "r"(b[1]));
}

// ---------------------------------------------------------------------------
// Zero deg + agg
// ---------------------------------------------------------------------------
__global__ void zero_kernel() {
    int i = blockIdx.x * blockDim.x + threadIdx.x;
    int total = N_NODES * LATENT;
    if (i < total) g_agg[i] = 0.0f;
    if (i < N_NODES) g_deg[i] = 0.0f;
}

// ---------------------------------------------------------------------------
// h = x @ Wg   [5120,256] @ [256,128]
// ---------------------------------------------------------------------------
__global__ __launch_bounds__(128) void gemm_h_kernel(
    const float* __restrict__ x, const float* __restrict__ Wg) {
    __shared__ float xs[4][TBL];
    int node0 = blockIdx.x * 4;
    int j = threadIdx.x;

    for (int idx = threadIdx.x; idx < 4 * TBL; idx += 128) {
        xs[idx / TBL][idx % TBL] = x[node0 * TBL + idx];
    }
    __syncthreads();

    float acc0 = 0.f, acc1 = 0.f, acc2 = 0.f, acc3 = 0.f;
#pragma unroll 4
    for (int k = 0; k < TBL; k++) {
        float w = Wg[k * LATENT + j];
        acc0 += xs[0][k] * w;
        acc1 += xs[1][k] * w;
        acc2 += xs[2][k] * w;
        acc3 += xs[3][k] * w;
    }
    g_h[(node0 + 0) * LATENT + j] = acc0;
    g_h[(node0 + 1) * LATENT + j] = acc1;
    g_h[(node0 + 2) * LATENT + j] = acc2;
    g_h[(node0 + 3) * LATENT + j] = acc3;
}

// ---------------------------------------------------------------------------
// Degree + dinv
// ---------------------------------------------------------------------------
__global__ void deg_kernel(const int* __restrict__ ei) {
    int e = blockIdx.x * blockDim.x + threadIdx.x;
    if (e < N_EDGES) atomicAdd(&g_deg[ei[N_EDGES + e]], 1.0f);
}

__global__ void dinv_kernel() {
    int i = blockIdx.x * blockDim.x + threadIdx.x;
    if (i < N_NODES) {
        float d = g_deg[i];
        g_dinv[i] = (d > 0.0f) ? rsqrtf(fmaxf(d, 1.0f)) : 0.0f;
    }
}

// ---------------------------------------------------------------------------
// agg[dst] += h[src] * (dinv[src]*dinv[dst]); one warp per edge, vector red.
// ---------------------------------------------------------------------------
__global__ __launch_bounds__(256) void scatter_kernel(const int* __restrict__ ei) {
    long long tid = (long long)blockIdx.x * blockDim.x + threadIdx.x;
    int e = (int)(tid >> 5);
    int lane = (int)(tid & 31);
    if (e >= N_EDGES) return;
    int s = ei[e];
    int d = ei[N_EDGES + e];
    float norm = g_dinv[s] * g_dinv[d];
    float4 v = reinterpret_cast<const float4*>(&g_h[(size_t)s * LATENT])[lane];
    float* ag = &g_agg[(size_t)d * LATENT + lane * 4];
    asm volatile("red.global.add.v4.f32 [%0], {%1, %2, %3, %4};"
                 :: "l"(ag), "f"(v.x * norm), "f"(v.y * norm),
                    "f"(v.z * norm), "f"(v.w * norm)
                 : "memory");
}

// ---------------------------------------------------------------------------
// Per-graph: z = relu(agg + bg); zz[n][m] = sum_l z[n][l]*z[m][l]
// Output written directly as bf16 hi/lo split (consumed by GEMM1).
// ---------------------------------------------------------------------------
#define ZT_STRIDE 84
__global__ __launch_bounds__(256) void outer_kernel(const float* __restrict__ bg) {
    __shared__ alignas(16) float zsT[LATENT][ZT_STRIDE];
    int g = blockIdx.x;

    for (int idx = threadIdx.x; idx < N_NEURONS * LATENT; idx += 256) {
        int n = idx >> 7;
        int l = idx & 127;
        float v = g_agg[((size_t)g * N_NEURONS + n) * LATENT + l] + bg[l];
        zsT[l][n] = v > 0.0f ? v : 0.0f;
    }
    __syncthreads();

    for (int p = threadIdx.x; p < N2 / 4; p += 256) {
        int n = p / (N_NEURONS / 4);
        int m0 = (p % (N_NEURONS / 4)) * 4;
        float4 acc = make_float4(0.f, 0.f, 0.f, 0.f);
#pragma unroll 4
        for (int l = 0; l < LATENT; l++) {
            float a = zsT[l][n];
            float4 v = *reinterpret_cast<const float4*>(&zsT[l][m0]);
            acc.x += a * v.x; acc.y += a * v.y; acc.z += a * v.z; acc.w += a * v.w;
        }
        size_t o = (size_t)g * N2 + n * N_NEURONS + m0;
        __nv_bfloat162 h0 = __floats2bfloat162_rn(acc.x, acc.y);
        __nv_bfloat162 h1 = __floats2bfloat162_rn(acc.z, acc.w);
        __nv_bfloat162 l0 = __floats2bfloat162_rn(acc.x - __bfloat162float(h0.x),
                                                  acc.y - __bfloat162float(h0.y));
        __nv_bfloat162 l1 = __floats2bfloat162_rn(acc.z - __bfloat162float(h1.x),
                                                  acc.w - __bfloat162float(h1.y));
        *reinterpret_cast<__nv_bfloat162*>(&g_zz_hi[o])     = h0;
        *reinterpret_cast<__nv_bfloat162*>(&g_zz_hi[o + 2]) = h1;
        *reinterpret_cast<__nv_bfloat162*>(&g_zz_lo[o])     = l0;
        *reinterpret_cast<__nv_bfloat162*>(&g_zz_lo[o + 2]) = l1;
    }
}

// ---------------------------------------------------------------------------
// Tensor-core split-K GEMM, bf16 hi/lo 3-term split (~fp32 accuracy).
//   A arrives pre-split as bf16 hi/lo globals -> cp.async straight into smem.
//   W converted in-loop into dedup [hi|lo] layout (2 stores/elem, not 3).
//   Fragments loaded once per K-iter (8 ldmatrix), 3 product phases from regs:
//     acc += Ahi*Whi + Alo*Whi + Ahi*Wlo
//   __launch_bounds__(256,3): cap regs so 400 blocks fit in ONE wave (3/SM).
// ---------------------------------------------------------------------------
#define BM 64
#define BN 128
#define KTO 16
#define AS2 40          // A_sm stride in bf16 (80B rows: conflict-free ldmatrix)
#define WS_STRIDE 136   // W_sm stride in bf16

__global__ __launch_bounds__(256, 3) void gemm_mma_splitk(
    const __nv_bfloat16* __restrict__ Ahi, const __nv_bfloat16* __restrict__ Alo,
    const float* __restrict__ W,
    float* __restrict__ partial, int K, int N, int Kchunk) {
    __shared__ __nv_bfloat16 A_sm[2][BM][AS2];            // hi k0-15, lo k16-31
    __shared__ __nv_bfloat16 W_sm[2 * KTO][WS_STRIDE];    // hi rows 0-15, lo 16-31
    __shared__ alignas(16) float Ws_stage[2][KTO][BN];

    int tid = threadIdx.x;
    int wid = tid >> 5, lane = tid & 31;
    int warp_m = wid & 1;
    int warp_n = wid >> 1;
    int n0 = blockIdx.x * BN;
    int sk = blockIdx.y;
    int kbase = sk * Kchunk;
    int T = Kchunk / KTO;

    float acc[2][4][4];
#pragma unroll
    for (int mi = 0; mi < 2; mi++)
#pragma unroll
        for (int ni = 0; ni < 4; ni++)
#pragma unroll
            for (int c = 0; c < 4; c++) acc[mi][ni][c] = 0.0f;

    // A loader: 256 cp.async16 (one per thread): m=tid>>2, half=(tid>>1)&1, chunk=tid&1
    int a_m = tid >> 2;
    int a_half = (tid >> 1) & 1;
    int a_chunk = tid & 1;
    const __nv_bfloat16* a_src_base =
        (a_half ? Alo : Ahi) + (size_t)a_m * K + a_chunk * 8;
    __nv_bfloat16* a_dst = &A_sm[0][a_m][a_half * 16 + a_chunk * 8];

    auto issue = [&](int s, int k0) {
        cp_async16(a_dst + (size_t)s * BM * AS2, a_src_base + k0);
#pragma unroll
        for (int i = 0; i < 2; i++) {
            int c = tid + i * 256;
            int kk = c >> 5, n4 = (c & 31) * 4;
            cp_async16(&Ws_stage[s][kk][n4], &W[(size_t)(k0 + kk) * N + n0 + n4]);
        }
        cp_commit();
    };

    issue(0, kbase);

    int g8 = lane >> 3, r8 = lane & 7;
    int row_off = (g8 & 1) * 8 + r8;
    int col_off = (g8 >> 1) * 8;

    for (int t = 0; t < T; t++) {
        cp_wait<0>();
        __syncthreads();   // stage t visible; all warps past iter t-1 mma

        int s = t & 1;
        if (t + 1 < T) issue(s ^ 1, kbase + (t + 1) * KTO);

        // Convert W: 1024 float2 pairs -> 4 per thread, dedup [hi|lo]
#pragma unroll
        for (int i = 0; i < 4; i++) {
            int idx = tid + i * 256;
            int kk = idx >> 6, np = idx & 63;
            float2 f = *reinterpret_cast<const float2*>(&Ws_stage[s][kk][np * 2]);
            __nv_bfloat162 hi = __floats2bfloat162_rn(f.x, f.y);
            __nv_bfloat162 lo = __floats2bfloat162_rn(
                f.x - __bfloat162float(hi.x), f.y - __bfloat162float(hi.y));
            *(__nv_bfloat162*)&W_sm[kk][np * 2]       = hi;
            *(__nv_bfloat162*)&W_sm[KTO + kk][np * 2] = lo;
        }
        __syncthreads();   // bf16 W ready

        // Load all fragments once
        uint32_t ah[2][4], al[2][4], bh[2][4], bl[2][4];
#pragma unroll
        for (int mi = 0; mi < 2; mi++) {
            const __nv_bfloat16* ab = &A_sm[s][warp_m * 32 + mi * 16 + row_off][0];
            ldm_x4(ah[mi], ab + col_off);
            ldm_x4(al[mi], ab + 16 + col_off);
        }
#pragma unroll
        for (int ni = 0; ni < 2; ni++) {
            int wc = warp_n * 32 + ni * 16 + col_off;
            ldm_x4_t(bh[ni], &W_sm[row_off][wc]);
            ldm_x4_t(bl[ni], &W_sm[KTO + row_off][wc]);
        }
        // 3 product phases from registers
#pragma unroll
        for (int mi = 0; mi < 2; mi++) {
            mma_bf16(acc[mi][0], ah[mi], &bh[0][0]);
            mma_bf16(acc[mi][1], ah[mi], &bh[0][2]);
            mma_bf16(acc[mi][2], ah[mi], &bh[1][0]);
            mma_bf16(acc[mi][3], ah[mi], &bh[1][2]);
        }
#pragma unroll
        for (int mi = 0; mi < 2; mi++) {
            mma_bf16(acc[mi][0], al[mi], &bh[0][0]);
            mma_bf16(acc[mi][1], al[mi], &bh[0][2]);
            mma_bf16(acc[mi][2], al[mi], &bh[1][0]);
            mma_bf16(acc[mi][3], al[mi], &bh[1][2]);
        }
#pragma unroll
        for (int mi = 0; mi < 2; mi++) {
            mma_bf16(acc[mi][0], ah[mi], &bl[0][0]);
            mma_bf16(acc[mi][1], ah[mi], &bl[0][2]);
            mma_bf16(acc[mi][2], ah[mi], &bl[1][0]);
            mma_bf16(acc[mi][3], ah[mi], &bl[1][2]);
        }
        // no trailing sync: next iter's first barrier guards smem reuse
    }

    int gq = lane >> 2, c2 = (lane & 3) * 2;
#pragma unroll
    for (int mi = 0; mi < 2; mi++)
#pragma unroll
        for (int ni = 0; ni < 4; ni++) {
            int col = n0 + warp_n * 32 + ni * 8 + c2;
            int row0 = warp_m * 32 + mi * 16 + gq;
            float* base = &partial[((size_t)sk * BM + row0) * N + col];
            *reinterpret_cast<float2*>(base) =
                make_float2(acc[mi][ni][0], acc[mi][ni][1]);
            *reinterpret_cast<float2*>(base + 8 * (size_t)N) =
                make_float2(acc[mi][ni][2], acc[mi][ni][3]);
        }
}

// ---------------------------------------------------------------------------
// Epilog1: sum split-K partials + bias + relu -> z1 as bf16 hi/lo
// ---------------------------------------------------------------------------
__global__ __launch_bounds__(256) void epilog1_kernel(const float* __restrict__ b1) {
    int i = blockIdx.x * blockDim.x + threadIdx.x;
    int total4 = N_GRAPHS * H1 / 4;
    if (i >= total4) return;
    const float4* p = reinterpret_cast<const float4*>(g_p1);
    float4 s = p[i];
#pragma unroll
    for (int sk = 1; sk < SK1; sk++) {
        float4 v = p[(size_t)sk * total4 + i];
        s.x += v.x; s.y += v.y; s.z += v.z; s.w += v.w;
    }
    int col = (i * 4) % H1;
    float4 b = *reinterpret_cast<const float4*>(&b1[col]);
    s.x = fmaxf(s.x + b.x, 0.0f);
    s.y = fmaxf(s.y + b.y, 0.0f);
    s.z = fmaxf(s.z + b.z, 0.0f);
    s.w = fmaxf(s.w + b.w, 0.0f);
    size_t o = (size_t)i * 4;
    __nv_bfloat162 h0 = __floats2bfloat162_rn(s.x, s.y);
    __nv_bfloat162 h1 = __floats2bfloat162_rn(s.z, s.w);
    __nv_bfloat162 l0 = __floats2bfloat162_rn(s.x - __bfloat162float(h0.x),
                                              s.y - __bfloat162float(h0.y));
    __nv_bfloat162 l1 = __floats2bfloat162_rn(s.z - __bfloat162float(h1.x),
                                              s.w - __bfloat162float(h1.y));
    *reinterpret_cast<__nv_bfloat162*>(&g_z1_hi[o])     = h0;
    *reinterpret_cast<__nv_bfloat162*>(&g_z1_hi[o + 2]) = h1;
    *reinterpret_cast<__nv_bfloat162*>(&g_z1_lo[o])     = l0;
    *reinterpret_cast<__nv_bfloat162*>(&g_z1_lo[o + 2]) = l1;
}

__global__ __launch_bounds__(256) void epilog2_kernel(const float* __restrict__ b2,
                                                      float* __restrict__ out) {
    int i = blockIdx.x * blockDim.x + threadIdx.x;
    int total4 = N_GRAPHS * N2 / 4;
    if (i >= total4) return;
    const float4* p = reinterpret_cast<const float4*>(g_p2);
    float4 s = p[i];
#pragma unroll
    for (int sk = 1; sk < SK2; sk++) {
        float4 v = p[(size_t)sk * total4 + i];
        s.x += v.x; s.y += v.y; s.z += v.z; s.w += v.w;
    }
    int col = (i * 4) % N2;
    float4 b = *reinterpret_cast<const float4*>(&b2[col]);
    s.x = 1.0f / (1.0f + __expf(-(s.x + b.x)));
    s.y = 1.0f / (1.0f + __expf(-(s.y + b.y)));
    s.z = 1.0f / (1.0f + __expf(-(s.z + b.z)));
    s.w = 1.0f / (1.0f + __expf(-(s.w + b.w)));
    reinterpret_cast<float4*>(out)[i] = s;
}

// ---------------------------------------------------------------------------
extern "C" void kernel_launch(void* const* d_in, const int* in_sizes, int n_in,
                              void* d_out, int out_size) {
    const float* x  = (const float*)d_in[0];
    const int* ei   = (const int*)d_in[1];
    const float* Wg = (const float*)d_in[2];
    const float* bg = (const float*)d_in[3];
    const float* W1 = (const float*)d_in[4];
    const float* b1 = (const float*)d_in[5];
    const float* W2 = (const float*)d_in[6];
    const float* b2 = (const float*)d_in[7];
    float* out = (float*)d_out;

    float *p1, *p2;
    __nv_bfloat16 *zzh, *zzl, *z1h, *z1l;
    cudaGetSymbolAddress((void**)&p1, g_p1);
    cudaGetSymbolAddress((void**)&p2, g_p2);
    cudaGetSymbolAddress((void**)&zzh, g_zz_hi);
    cudaGetSymbolAddress((void**)&zzl, g_zz_lo);
    cudaGetSymbolAddress((void**)&z1h, g_z1_hi);
    cudaGetSymbolAddress((void**)&z1l, g_z1_lo);

    // 1. zero deg + agg
    {
        int total = N_NODES * LATENT;
        zero_kernel<<<(total + 255) / 256, 256>>>();
    }
    // 2. h = x @ Wg
    gemm_h_kernel<<<N_NODES / 4, 128>>>(x, Wg);
    // 3. degree
    deg_kernel<<<(N_EDGES + 255) / 256, 256>>>(ei);
    // 4. dinv
    dinv_kernel<<<(N_NODES + 255) / 256, 256>>>();
    // 5. scatter-add messages (vector red)
    {
        long long threads = (long long)N_EDGES * 32;
        scatter_kernel<<<(unsigned)((threads + 255) / 256), 256>>>(ei);
    }
    // 6. relu + per-graph outer product -> zz (bf16 hi/lo)
    outer_kernel<<<N_GRAPHS, 256>>>(bg);
    // 7. GEMM1 partials: [64,6400]@[6400,12800], split-K=4 -> 400 blocks
    {
        dim3 grid(H1 / BN, SK1);
        gemm_mma_splitk<<<grid, 256>>>(zzh, zzl, W1, p1, N2, H1, N2 / SK1);
    }
    // 8. z1 = relu(sum + b1) -> bf16 hi/lo
    {
        int total4 = N_GRAPHS * H1 / 4;
        epilog1_kernel<<<(total4 + 255) / 256, 256>>>(b1);
    }
    // 9. GEMM2 partials: [64,12800]@[12800,6400], split-K=8 -> 400 blocks
    {
        dim3 grid(N2 / BN, SK2);
        gemm_mma_splitk<<<grid, 256>>>(z1h, z1l, W2, p2, H1, N2, H1 / SK2);
    }
    // 10. out = sigmoid(sum + b2)
    {
        int total4 = N_GRAPHS * N2 / 4;
        epilog2_kernel<<<(total4 + 255) / 256, 256>>>(b2, out);
    }
}